// round 6
// baseline (speedup 1.0000x reference)
#include <cuda_runtime.h>
#include <cuda_bf16.h>
#include <stdint.h>
#include <math.h>

typedef unsigned int u32;

#define S_LEN   2048
#define HID     4096
#define NH      32
#define NKV     8
#define HD      128
#define WINDOW  1024
#define SCALE_F 0.08838834764831845f   // 1/sqrt(128)

// ---------------------------------------------------------------------------
// Scratch (device globals)
// ---------------------------------------------------------------------------
__device__ float g_q  [S_LEN * NH  * HD];
__device__ float g_k  [S_LEN * NKV * HD];
__device__ float g_v  [S_LEN * NKV * HD];
__device__ float g_cos[S_LEN * (HD / 2)];
__device__ float g_sin[S_LEN * (HD / 2)];

// attention operands (bf16 hi/lo)
__device__ __nv_bfloat16 g_qhi[S_LEN * NH  * HD];
__device__ __nv_bfloat16 g_qlo[S_LEN * NH  * HD];
__device__ __nv_bfloat16 g_khi[S_LEN * NKV * HD];
__device__ __nv_bfloat16 g_klo[S_LEN * NKV * HD];
__device__ __nv_bfloat16 g_vthi[NKV * HD * S_LEN];   // [hk][d][s]
__device__ __nv_bfloat16 g_vtlo[NKV * HD * S_LEN];

// pre-split GEMM operands (u32 = bf16 k-pair words)
// A-style: [M][K/2] pairs along row.  B now TRANSPOSED: [N][K/2].
__device__ u32 g_hshi[S_LEN * HID / 2];
__device__ u32 g_hslo[S_LEN * HID / 2];
__device__ u32 g_wqhi[(NH  * HD) * HID / 2];
__device__ u32 g_wqlo[(NH  * HD) * HID / 2];
__device__ u32 g_wkhi[(NKV * HD) * HID / 2];
__device__ u32 g_wklo[(NKV * HD) * HID / 2];
__device__ u32 g_wvhi[(NKV * HD) * HID / 2];
__device__ u32 g_wvlo[(NKV * HD) * HID / 2];
__device__ u32 g_wohi[HID * (NH * HD) / 2];
__device__ u32 g_wolo[HID * (NH * HD) / 2];
__device__ u32 g_athi[S_LEN * HID / 2];   // attention output, pre-split
__device__ u32 g_atlo[S_LEN * HID / 2];

// ---------------------------------------------------------------------------
// Helpers
// ---------------------------------------------------------------------------
__device__ __forceinline__ u32 pack_bf16(float e0, float e1) {
    __nv_bfloat162 p = __floats2bfloat162_rn(e0, e1);   // .x = e0 (low half)
    return *reinterpret_cast<u32*>(&p);
}

__device__ __forceinline__ void split_pair(float a, float b, u32& hi, u32& lo) {
    float ha = __bfloat162float(__float2bfloat16_rn(a));
    float hb = __bfloat162float(__float2bfloat16_rn(b));
    hi = pack_bf16(ha, hb);
    lo = pack_bf16(a - ha, b - hb);
}

__device__ __forceinline__ void cp16(u32* dst, const u32* src) {
    u32 s = (u32)__cvta_generic_to_shared(dst);
    asm volatile("cp.async.cg.shared.global [%0], [%1], 16;" :: "r"(s), "l"(src));
}

#define MMA_BF16(d, a0, a1, a2, a3, b0, b1)                                 \
    asm volatile(                                                           \
        "mma.sync.aligned.m16n8k16.row.col.f32.bf16.bf16.f32 "              \
        "{%0,%1,%2,%3}, {%4,%5,%6,%7}, {%8,%9}, {%0,%1,%2,%3};"             \
        : "+f"(d[0]), "+f"(d[1]), "+f"(d[2]), "+f"(d[3])                    \
        : "r"(a0), "r"(a1), "r"(a2), "r"(a3), "r"(b0), "r"(b1))

#define LDSM4(r0, r1, r2, r3, addr)                                         \
    asm volatile("ldmatrix.sync.aligned.m8n8.x4.shared.b16 "                \
                 "{%0,%1,%2,%3}, [%4];"                                     \
                 : "=r"(r0), "=r"(r1), "=r"(r2), "=r"(r3) : "r"(addr))

// ---------------------------------------------------------------------------
// Split kernels
// ---------------------------------------------------------------------------
// A-style: pairs along a row. total = M*K/2 words.
__global__ void split_A_kernel(const float* __restrict__ X,
                               u32* __restrict__ hi, u32* __restrict__ lo,
                               int total_words)
{
    int i = blockIdx.x * 256 + threadIdx.x;
    if (i >= total_words) return;
    float2 xy = *(const float2*)(X + (size_t)i * 2);
    split_pair(xy.x, xy.y, hi[i], lo[i]);
}

// Transpose-split: W[K][N] fp32 -> Wt hi/lo [N][K/2] pair-words.
// Grid (K/32, N/32), block (32,8).
__global__ __launch_bounds__(256) void split_BT_kernel(
    const float* __restrict__ W, u32* __restrict__ hi, u32* __restrict__ lo,
    int K, int N)
{
    __shared__ float tile[32][33];
    const int k0 = blockIdx.x * 32;
    const int n0 = blockIdx.y * 32;
    const int tx = threadIdx.x;
    const int ty = threadIdx.y;
    const int tid = ty * 32 + tx;

#pragma unroll
    for (int i = 0; i < 4; i++)
        tile[ty + i * 8][tx] = W[(size_t)(k0 + ty + i * 8) * N + n0 + tx];
    __syncthreads();

    const int Kp = K / 2;
#pragma unroll
    for (int i = 0; i < 2; i++) {
        int e  = tid + 256 * i;       // 0..511
        int nl = e >> 4;              // 0..31
        int kp = e & 15;              // 0..15
        u32 h, l;
        split_pair(tile[2 * kp][nl], tile[2 * kp + 1][nl], h, l);
        size_t o = (size_t)(n0 + nl) * Kp + (k0 >> 1) + kp;
        hi[o] = h;
        lo[o] = l;
    }
}

// ---------------------------------------------------------------------------
// Pre-split bf16x3 GEMM, cp.async double-buffered, ldmatrix fragment loads.
// C[M,N] = A[M,K] @ B[K,N]; A: [M][Kp] pair-words, Bt: [N][Kp] pair-words.
// Block tile 128x128, BK=32 (16 pair-words), 256 threads.
// Smem per operand tile: [128][RS=20] words (16 data + 4 pad) — conflict-free
// for both cp.async (16B) and ldmatrix (20*l mod 32 spans all 8 groups).
// ---------------------------------------------------------------------------
#define RS 20
#define STG_T   (128 * RS)                    // 2560 words per tile
#define STG_WORDS (4 * STG_T)                 // AsHi,AsLo,BsHi,BsLo = 10240
#define GEMM_SMEM_BYTES (2 * STG_WORDS * 4)   // 81920 B

__global__ __launch_bounds__(256, 2) void gemm_pre(
    const u32* __restrict__ Ahi, const u32* __restrict__ Alo,
    const u32* __restrict__ Bhi, const u32* __restrict__ Blo,
    float* __restrict__ C, int M, int N, int Kp)
{
    extern __shared__ u32 smem[];
    const u32 sbase = (u32)__cvta_generic_to_shared(smem);

    const int tid    = threadIdx.x;
    const int warp   = tid >> 5;
    const int lane   = tid & 31;
    const int wm     = (warp >> 2) * 64;
    const int wn     = (warp & 3)  * 32;
    const int bm     = blockIdx.y * 128;
    const int bn     = blockIdx.x * 128;
    const int r      = lane >> 2;
    const int t      = lane & 3;
    const int lane15 = lane & 15;
    const int lanehi = lane >> 4;      // 0/1

    float acc[4][4][4];
#pragma unroll
    for (int mi = 0; mi < 4; mi++)
#pragma unroll
        for (int ni = 0; ni < 4; ni++)
#pragma unroll
            for (int c = 0; c < 4; c++) acc[mi][ni][c] = 0.f;

    const int KT = Kp / 16;

    auto load_stage = [&](int kt, int buf) {
        u32* base = smem + buf * STG_WORDS;
        u32* sAhi = base;
        u32* sAlo = base + STG_T;
        u32* sBhi = base + 2 * STG_T;
        u32* sBlo = base + 3 * STG_T;
        int kp0 = kt * 16;
#pragma unroll
        for (int i = 0; i < 2; i++) {
            int e   = tid + 256 * i;       // 0..511
            int row = e >> 2;
            int c   = e & 3;
            const size_t ga = (size_t)(bm + row) * Kp + kp0 + c * 4;
            const size_t gb = (size_t)(bn + row) * Kp + kp0 + c * 4;
            cp16(&sAhi[row * RS + c * 4], Ahi + ga);
            cp16(&sAlo[row * RS + c * 4], Alo + ga);
            cp16(&sBhi[row * RS + c * 4], Bhi + gb);
            cp16(&sBlo[row * RS + c * 4], Blo + gb);
        }
    };

    load_stage(0, 0);
    asm volatile("cp.async.commit_group;");

    for (int kt = 0; kt < KT; kt++) {
        if (kt + 1 < KT) {
            load_stage(kt + 1, (kt + 1) & 1);
            asm volatile("cp.async.commit_group;");
            asm volatile("cp.async.wait_group 1;");
        } else {
            asm volatile("cp.async.wait_group 0;");
        }
        __syncthreads();

        const u32 stg  = sbase + ((kt & 1) * STG_WORDS) * 4;
        const u32 aHiS = stg;
        const u32 aLoS = stg + STG_T * 4;
        const u32 bHiS = stg + 2 * STG_T * 4;
        const u32 bLoS = stg + 3 * STG_T * 4;

#pragma unroll
        for (int ks = 0; ks < 2; ks++) {
            const u32 koff = (ks * 8 + lanehi * 4) * 4;   // byte offset in row
            u32 bh[2][4], bl[2][4];
#pragma unroll
            for (int p = 0; p < 2; p++) {
                const u32 rowoff = ((wn + p * 16 + lane15) * RS) * 4 + koff;
                LDSM4(bh[p][0], bh[p][1], bh[p][2], bh[p][3], bHiS + rowoff);
                LDSM4(bl[p][0], bl[p][1], bl[p][2], bl[p][3], bLoS + rowoff);
            }
#pragma unroll
            for (int mi = 0; mi < 4; mi++) {
                const u32 rowoff = ((wm + mi * 16 + lane15) * RS) * 4 + koff;
                u32 ah0, ah1, ah2, ah3, al0, al1, al2, al3;
                LDSM4(ah0, ah1, ah2, ah3, aHiS + rowoff);
                LDSM4(al0, al1, al2, al3, aLoS + rowoff);
#pragma unroll
                for (int ni = 0; ni < 4; ni++) {
                    int p = ni >> 1, ix = ni & 1;
                    u32 b0h = bh[p][ix], b1h = bh[p][ix + 2];
                    u32 b0l = bl[p][ix], b1l = bl[p][ix + 2];
                    MMA_BF16(acc[mi][ni], ah0, ah1, ah2, ah3, b0h, b1h);
                    MMA_BF16(acc[mi][ni], ah0, ah1, ah2, ah3, b0l, b1l);
                    MMA_BF16(acc[mi][ni], al0, al1, al2, al3, b0h, b1h);
                }
            }
        }
        __syncthreads();
    }

#pragma unroll
    for (int mi = 0; mi < 4; mi++) {
#pragma unroll
        for (int ni = 0; ni < 4; ni++) {
            int row = bm + wm + mi * 16 + r;
            int col = bn + wn + ni * 8 + t * 2;
            *(float2*)(C + (size_t)row * N + col) =
                make_float2(acc[mi][ni][0], acc[mi][ni][1]);
            *(float2*)(C + (size_t)(row + 8) * N + col) =
                make_float2(acc[mi][ni][2], acc[mi][ni][3]);
        }
    }
}

// ---------------------------------------------------------------------------
// RoPE
// ---------------------------------------------------------------------------
__global__ void rope_tables_kernel()
{
    int s = blockIdx.x;
    int d = threadIdx.x;
    double invf = pow(10000.0, -(double)(2 * d) / 128.0);
    float  ang  = (float)s * (float)invf;
    g_cos[s * 64 + d] = (float)cos((double)ang);
    g_sin[s * 64 + d] = (float)sin((double)ang);
}

__global__ void rope_split_kernel(const float* __restrict__ x,
                                  __nv_bfloat16* __restrict__ xhi,
                                  __nv_bfloat16* __restrict__ xlo,
                                  int nheads)
{
    int idx = blockIdx.x * 256 + threadIdx.x;
    int total = S_LEN * nheads * 64;
    if (idx >= total) return;
    int d = idx & 63;
    int t = idx >> 6;
    int h = t % nheads;
    int s = t / nheads;
    float c  = g_cos[s * 64 + d];
    float sn = g_sin[s * 64 + d];
    size_t base = ((size_t)s * nheads + h) * HD;
    float x0 = x[base + d];
    float x1 = x[base + d + 64];
    float r0 = x0 * c - x1 * sn;
    float r1 = x1 * c + x0 * sn;
    float h0 = __bfloat162float(__float2bfloat16_rn(r0));
    float h1 = __bfloat162float(__float2bfloat16_rn(r1));
    xhi[base + d]      = __float2bfloat16_rn(h0);
    xhi[base + d + 64] = __float2bfloat16_rn(h1);
    xlo[base + d]      = __float2bfloat16_rn(r0 - h0);
    xlo[base + d + 64] = __float2bfloat16_rn(r1 - h1);
}

// ---------------------------------------------------------------------------
// V split + transpose: g_v [s][hk][d] -> g_vt{hi,lo} [hk][d][s]
// ---------------------------------------------------------------------------
__global__ __launch_bounds__(256) void v_split_transpose_kernel()
{
    __shared__ float tile[32][33];
    const int s0 = blockIdx.x * 32;
    const int d0 = blockIdx.y * 32;
    const int hk = blockIdx.z;
    const int tx = threadIdx.x;
    const int ty = threadIdx.y;

#pragma unroll
    for (int i = 0; i < 4; i++) {
        int s = s0 + ty + i * 8;
        tile[ty + i * 8][tx] = g_v[((size_t)s * NKV + hk) * HD + d0 + tx];
    }
    __syncthreads();
#pragma unroll
    for (int i = 0; i < 4; i++) {
        int d = d0 + ty + i * 8;
        float val = tile[tx][ty + i * 8];
        float hi  = __bfloat162float(__float2bfloat16_rn(val));
        size_t o  = ((size_t)hk * HD + d) * S_LEN + s0 + tx;
        g_vthi[o] = __float2bfloat16_rn(hi);
        g_vtlo[o] = __float2bfloat16_rn(val - hi);
    }
}

// ---------------------------------------------------------------------------
// Tensor-core flash attention (bf16x3) — unchanged from R5.
// ---------------------------------------------------------------------------
#define RSQ 68
#define RSV 36
#define SM_QHI 0
#define SM_QLO (64 * RSQ)
#define SM_KHI (2 * 64 * RSQ)
#define SM_KLO (3 * 64 * RSQ)
#define SM_VHI (4 * 64 * RSQ)
#define SM_VLO (4 * 64 * RSQ + 128 * RSV)
#define ATT_SMEM_WORDS (4 * 64 * RSQ + 2 * 128 * RSV)

__global__ __launch_bounds__(128) void attn_mma_kernel(
    const __nv_bfloat16* __restrict__ qhi, const __nv_bfloat16* __restrict__ qlo,
    const __nv_bfloat16* __restrict__ khi, const __nv_bfloat16* __restrict__ klo,
    const __nv_bfloat16* __restrict__ vthi, const __nv_bfloat16* __restrict__ vtlo,
    u32* __restrict__ athi, u32* __restrict__ atlo)
{
    extern __shared__ u32 sm[];
    u32* Qhi = sm + SM_QHI;
    u32* Qlo = sm + SM_QLO;
    u32* Khi = sm + SM_KHI;
    u32* Klo = sm + SM_KLO;
    u32* Vhi = sm + SM_VHI;
    u32* Vlo = sm + SM_VLO;

    const int tid  = threadIdx.x;
    const int warp = tid >> 5;
    const int lane = tid & 31;
    const int g    = lane >> 2;
    const int t4   = lane & 3;
    const int q0   = blockIdx.x * 64;
    const int h    = blockIdx.y;
    const int hk   = h >> 2;
    const int wrow = warp * 16;

    const float NEGINF = __int_as_float(0xff800000);

#pragma unroll
    for (int it = 0; it < 8; it++) {
        int e   = tid + 128 * it;
        int row = e >> 4;
        int c   = e & 15;
        size_t gb = ((size_t)(q0 + row) * NH + h) * HD + c * 8;
        *(uint4*)&Qhi[row * RSQ + c * 4] = *(const uint4*)(qhi + gb);
        *(uint4*)&Qlo[row * RSQ + c * 4] = *(const uint4*)(qlo + gb);
    }

    const int i0 = q0 + wrow + g;
    const int i1 = i0 + 8;

    float oacc[16][4];
#pragma unroll
    for (int n = 0; n < 16; n++)
#pragma unroll
        for (int c = 0; c < 4; c++) oacc[n][c] = 0.f;
    float m0 = -1e30f, m1 = -1e30f, l0 = 0.f, l1 = 0.f;

    int lo_j = q0 - (WINDOW - 1);
    if (lo_j < 0) lo_j = 0;
    const int jt_lo = lo_j >> 6;
    const int jt_hi = q0 >> 6;

    for (int jt = jt_lo; jt <= jt_hi; jt++) {
        const int j0 = jt << 6;
        __syncthreads();
#pragma unroll
        for (int it = 0; it < 8; it++) {
            int e = tid + 128 * it;
            {
                int row = e >> 4, c = e & 15;
                size_t gb = ((size_t)(j0 + row) * NKV + hk) * HD + c * 8;
                *(uint4*)&Khi[row * RSQ + c * 4] = *(const uint4*)(khi + gb);
                *(uint4*)&Klo[row * RSQ + c * 4] = *(const uint4*)(klo + gb);
            }
            {
                int d = e >> 3, c = e & 7;
                size_t gb = ((size_t)hk * HD + d) * S_LEN + j0 + c * 8;
                *(uint4*)&Vhi[d * RSV + c * 4] = *(const uint4*)(vthi + gb);
                *(uint4*)&Vlo[d * RSV + c * 4] = *(const uint4*)(vtlo + gb);
            }
        }
        __syncthreads();

        float sacc[8][4];
#pragma unroll
        for (int n = 0; n < 8; n++)
#pragma unroll
            for (int c = 0; c < 4; c++) sacc[n][c] = 0.f;

#pragma unroll
        for (int kt = 0; kt < 8; kt++) {
            int ao = (wrow + g) * RSQ + kt * 8 + t4;
            u32 qh0 = Qhi[ao];
            u32 qh1 = Qhi[ao + 8 * RSQ];
            u32 qh2 = Qhi[ao + 4];
            u32 qh3 = Qhi[ao + 8 * RSQ + 4];
            u32 ql0 = Qlo[ao];
            u32 ql1 = Qlo[ao + 8 * RSQ];
            u32 ql2 = Qlo[ao + 4];
            u32 ql3 = Qlo[ao + 8 * RSQ + 4];
#pragma unroll
            for (int nt = 0; nt < 8; nt++) {
                int bo = (nt * 8 + g) * RSQ + kt * 8 + t4;
                u32 bh0 = Khi[bo], bh1 = Khi[bo + 4];
                u32 bl0 = Klo[bo], bl1 = Klo[bo + 4];
                MMA_BF16(sacc[nt], qh0, qh1, qh2, qh3, bh0, bh1);
                MMA_BF16(sacc[nt], qh0, qh1, qh2, qh3, bl0, bl1);
                MMA_BF16(sacc[nt], ql0, ql1, ql2, ql3, bh0, bh1);
            }
        }

        bool full = (j0 + 63 <= q0 + wrow) && (j0 > q0 + wrow + 15 - WINDOW);
        if (full) {
#pragma unroll
            for (int nt = 0; nt < 8; nt++)
#pragma unroll
                for (int c = 0; c < 4; c++) sacc[nt][c] *= SCALE_F;
        } else {
#pragma unroll
            for (int nt = 0; nt < 8; nt++) {
                int jb = j0 + nt * 8 + 2 * t4;
                bool a00 = (jb     <= i0) && (jb     > i0 - WINDOW);
                bool a01 = (jb + 1 <= i0) && (jb + 1 > i0 - WINDOW);
                bool a10 = (jb     <= i1) && (jb     > i1 - WINDOW);
                bool a11 = (jb + 1 <= i1) && (jb + 1 > i1 - WINDOW);
                sacc[nt][0] = a00 ? sacc[nt][0] * SCALE_F : NEGINF;
                sacc[nt][1] = a01 ? sacc[nt][1] * SCALE_F : NEGINF;
                sacc[nt][2] = a10 ? sacc[nt][2] * SCALE_F : NEGINF;
                sacc[nt][3] = a11 ? sacc[nt][3] * SCALE_F : NEGINF;
            }
        }

        float mx0 = -1e30f, mx1 = -1e30f;
#pragma unroll
        for (int nt = 0; nt < 8; nt++) {
            mx0 = fmaxf(mx0, fmaxf(sacc[nt][0], sacc[nt][1]));
            mx1 = fmaxf(mx1, fmaxf(sacc[nt][2], sacc[nt][3]));
        }
        mx0 = fmaxf(mx0, __shfl_xor_sync(0xffffffffu, mx0, 1));
        mx0 = fmaxf(mx0, __shfl_xor_sync(0xffffffffu, mx0, 2));
        mx1 = fmaxf(mx1, __shfl_xor_sync(0xffffffffu, mx1, 1));
        mx1 = fmaxf(mx1, __shfl_xor_sync(0xffffffffu, mx1, 2));
        float mn0 = fmaxf(m0, mx0);
        float mn1 = fmaxf(m1, mx1);
        float f0 = __expf(m0 - mn0);
        float f1 = __expf(m1 - mn1);
        float sum0 = 0.f, sum1 = 0.f;
#pragma unroll
        for (int nt = 0; nt < 8; nt++) {
            sacc[nt][0] = __expf(sacc[nt][0] - mn0); sum0 += sacc[nt][0];
            sacc[nt][1] = __expf(sacc[nt][1] - mn0); sum0 += sacc[nt][1];
            sacc[nt][2] = __expf(sacc[nt][2] - mn1); sum1 += sacc[nt][2];
            sacc[nt][3] = __expf(sacc[nt][3] - mn1); sum1 += sacc[nt][3];
        }
        sum0 += __shfl_xor_sync(0xffffffffu, sum0, 1);
        sum0 += __shfl_xor_sync(0xffffffffu, sum0, 2);
        sum1 += __shfl_xor_sync(0xffffffffu, sum1, 1);
        sum1 += __shfl_xor_sync(0xffffffffu, sum1, 2);
        l0 = l0 * f0 + sum0;  m0 = mn0;
        l1 = l1 * f1 + sum1;  m1 = mn1;

#pragma unroll
        for (int n = 0; n < 16; n++) {
            oacc[n][0] *= f0; oacc[n][1] *= f0;
            oacc[n][2] *= f1; oacc[n][3] *= f1;
        }

#pragma unroll
        for (int kt = 0; kt < 4; kt++) {
            float p00 = sacc[2*kt][0],   p01 = sacc[2*kt][1];
            float p02 = sacc[2*kt][2],   p03 = sacc[2*kt][3];
            float p10 = sacc[2*kt+1][0], p11 = sacc[2*kt+1][1];
            float p12 = sacc[2*kt+1][2], p13 = sacc[2*kt+1][3];
            float h00 = __bfloat162float(__float2bfloat16_rn(p00));
            float h01 = __bfloat162float(__float2bfloat16_rn(p01));
            float h02 = __bfloat162float(__float2bfloat16_rn(p02));
            float h03 = __bfloat162float(__float2bfloat16_rn(p03));
            float h10 = __bfloat162float(__float2bfloat16_rn(p10));
            float h11 = __bfloat162float(__float2bfloat16_rn(p11));
            float h12 = __bfloat162float(__float2bfloat16_rn(p12));
            float h13 = __bfloat162float(__float2bfloat16_rn(p13));
            u32 ah0 = pack_bf16(h00, h01);
            u32 ah1 = pack_bf16(h02, h03);
            u32 ah2 = pack_bf16(h10, h11);
            u32 ah3 = pack_bf16(h12, h13);
            u32 al0 = pack_bf16(p00 - h00, p01 - h01);
            u32 al1 = pack_bf16(p02 - h02, p03 - h03);
            u32 al2 = pack_bf16(p10 - h10, p11 - h11);
            u32 al3 = pack_bf16(p12 - h12, p13 - h13);
#pragma unroll
            for (int nt = 0; nt < 16; nt++) {
                int vo = (nt * 8 + g) * RSV + kt * 8 + t4;
                u32 vh0 = Vhi[vo], vh1 = Vhi[vo + 4];
                u32 vl0 = Vlo[vo], vl1 = Vlo[vo + 4];
                MMA_BF16(oacc[nt], ah0, ah1, ah2, ah3, vh0, vh1);
                MMA_BF16(oacc[nt], ah0, ah1, ah2, ah3, vl0, vl1);
                MMA_BF16(oacc[nt], al0, al1, al2, al3, vh0, vh1);
            }
        }
    }

    float inv0 = 1.0f / l0;
    float inv1 = 1.0f / l1;
#pragma unroll
    for (int nt = 0; nt < 16; nt++) {
        int col = nt * 8 + 2 * t4;
        int wcol = (h * HD + col) >> 1;
        size_t w0 = (size_t)i0 * (HID / 2) + wcol;
        size_t w1 = (size_t)i1 * (HID / 2) + wcol;
        u32 hi0, lo0, hi1, lo1;
        split_pair(oacc[nt][0] * inv0, oacc[nt][1] * inv0, hi0, lo0);
        split_pair(oacc[nt][2] * inv1, oacc[nt][3] * inv1, hi1, lo1);
        athi[w0] = hi0;  atlo[w0] = lo0;
        athi[w1] = hi1;  atlo[w1] = lo1;
    }
}

// ---------------------------------------------------------------------------
// kernel_launch
// ---------------------------------------------------------------------------
extern "C" void kernel_launch(void* const* d_in, const int* in_sizes, int n_in,
                              void* d_out, int out_size)
{
    (void)in_sizes; (void)n_in; (void)out_size;
    const float* hs = (const float*)d_in[0];
    const float* Wq = (const float*)d_in[3];
    const float* Wk = (const float*)d_in[4];
    const float* Wv = (const float*)d_in[5];
    const float* Wo = (const float*)d_in[6];
    float* out = (float*)d_out;

    float *q, *k, *v;
    __nv_bfloat16 *qhi, *qlo, *khi, *klo, *vthi, *vtlo;
    u32 *hshi, *hslo, *wqhi, *wqlo, *wkhi, *wklo, *wvhi, *wvlo, *wohi, *wolo;
    u32 *athi, *atlo;
    cudaGetSymbolAddress((void**)&q,    g_q);
    cudaGetSymbolAddress((void**)&k,    g_k);
    cudaGetSymbolAddress((void**)&v,    g_v);
    cudaGetSymbolAddress((void**)&qhi,  g_qhi);
    cudaGetSymbolAddress((void**)&qlo,  g_qlo);
    cudaGetSymbolAddress((void**)&khi,  g_khi);
    cudaGetSymbolAddress((void**)&klo,  g_klo);
    cudaGetSymbolAddress((void**)&vthi, g_vthi);
    cudaGetSymbolAddress((void**)&vtlo, g_vtlo);
    cudaGetSymbolAddress((void**)&hshi, g_hshi);
    cudaGetSymbolAddress((void**)&hslo, g_hslo);
    cudaGetSymbolAddress((void**)&wqhi, g_wqhi);
    cudaGetSymbolAddress((void**)&wqlo, g_wqlo);
    cudaGetSymbolAddress((void**)&wkhi, g_wkhi);
    cudaGetSymbolAddress((void**)&wklo, g_wklo);
    cudaGetSymbolAddress((void**)&wvhi, g_wvhi);
    cudaGetSymbolAddress((void**)&wvlo, g_wvlo);
    cudaGetSymbolAddress((void**)&wohi, g_wohi);
    cudaGetSymbolAddress((void**)&wolo, g_wolo);
    cudaGetSymbolAddress((void**)&athi, g_athi);
    cudaGetSymbolAddress((void**)&atlo, g_atlo);

    cudaFuncSetAttribute(gemm_pre,
                         cudaFuncAttributeMaxDynamicSharedMemorySize, GEMM_SMEM_BYTES);
    const int att_smem = ATT_SMEM_WORDS * (int)sizeof(u32);
    cudaFuncSetAttribute(attn_mma_kernel,
                         cudaFuncAttributeMaxDynamicSharedMemorySize, att_smem);

    // ---- operand pre-split ----
    {
        int wA = S_LEN * HID / 2;
        split_A_kernel<<<(wA + 255) / 256, 256>>>(hs, hshi, hslo, wA);
        split_BT_kernel<<<dim3(HID / 32, (NH * HD) / 32), dim3(32, 8)>>>(
            Wq, wqhi, wqlo, HID, NH * HD);
        split_BT_kernel<<<dim3(HID / 32, (NKV * HD) / 32), dim3(32, 8)>>>(
            Wk, wkhi, wklo, HID, NKV * HD);
        split_BT_kernel<<<dim3(HID / 32, (NKV * HD) / 32), dim3(32, 8)>>>(
            Wv, wvhi, wvlo, HID, NKV * HD);
        split_BT_kernel<<<dim3((NH * HD) / 32, HID / 32), dim3(32, 8)>>>(
            Wo, wohi, wolo, NH * HD, HID);
    }

    // ---- projections ----
    gemm_pre<<<dim3((NH*HD) / 128, S_LEN / 128), 256, GEMM_SMEM_BYTES>>>(
        hshi, hslo, wqhi, wqlo, q, S_LEN, NH * HD, HID / 2);
    gemm_pre<<<dim3((NKV*HD) / 128, S_LEN / 128), 256, GEMM_SMEM_BYTES>>>(
        hshi, hslo, wkhi, wklo, k, S_LEN, NKV * HD, HID / 2);
    gemm_pre<<<dim3((NKV*HD) / 128, S_LEN / 128), 256, GEMM_SMEM_BYTES>>>(
        hshi, hslo, wvhi, wvlo, v, S_LEN, NKV * HD, HID / 2);

    // ---- RoPE + splits ----
    rope_tables_kernel<<<S_LEN, 64>>>();
    rope_split_kernel<<<(S_LEN * NH  * 64 + 255) / 256, 256>>>(q, qhi, qlo, NH);
    rope_split_kernel<<<(S_LEN * NKV * 64 + 255) / 256, 256>>>(k, khi, klo, NKV);
    v_split_transpose_kernel<<<dim3(S_LEN / 32, HD / 32, NKV), dim3(32, 8)>>>();

    // ---- attention ----
    attn_mma_kernel<<<dim3(S_LEN / 64, NH), 128, att_smem>>>(
        qhi, qlo, khi, klo, vthi, vtlo, athi, atlo);

    // ---- output projection ----
    gemm_pre<<<dim3(HID / 128, S_LEN / 128), 256, GEMM_SMEM_BYTES>>>(
        athi, atlo, wohi, wolo, out, S_LEN, HID, NH * HD / 2);
}

// round 7
// speedup vs baseline: 1.1535x; 1.1535x over previous
#include <cuda_runtime.h>
#include <cuda_bf16.h>
#include <stdint.h>
#include <math.h>

typedef unsigned int u32;

#define S_LEN   2048
#define HID     4096
#define NH      32
#define NKV     8
#define HD      128
#define WINDOW  1024
#define NQKV    (NH * HD + 2 * NKV * HD)   // 6144 fused N
#define KOFF    (NH * HD)                  // 4096
#define VOFF    (NH * HD + NKV * HD)       // 5120
#define SCALE_F 0.08838834764831845f       // 1/sqrt(128)

// ---------------------------------------------------------------------------
// Scratch (device globals)
// ---------------------------------------------------------------------------
__device__ float g_qkv[S_LEN * NQKV];      // fused QKV fp32 [s][6144]
__device__ float g_cos[S_LEN * (HD / 2)];
__device__ float g_sin[S_LEN * (HD / 2)];

// attention operands (bf16 hi/lo)
__device__ __nv_bfloat16 g_qhi[S_LEN * NH  * HD];
__device__ __nv_bfloat16 g_qlo[S_LEN * NH  * HD];
__device__ __nv_bfloat16 g_khi[S_LEN * NKV * HD];
__device__ __nv_bfloat16 g_klo[S_LEN * NKV * HD];
__device__ __nv_bfloat16 g_vthi[NKV * HD * S_LEN];   // [hk][d][s]
__device__ __nv_bfloat16 g_vtlo[NKV * HD * S_LEN];

// pre-split GEMM operands (u32 = bf16 k-pair words)
// A: [M][K/2] pairs along row.  B (R5 layout): [K/2][N] pair-words.
__device__ u32 g_hshi[S_LEN * HID / 2];
__device__ u32 g_hslo[S_LEN * HID / 2];
__device__ u32 g_wqkvhi[HID / 2 * NQKV];   // fused weights [Kp][6144]
__device__ u32 g_wqkvlo[HID / 2 * NQKV];
__device__ u32 g_wohi[(NH * HD) / 2 * HID];
__device__ u32 g_wolo[(NH * HD) / 2 * HID];
__device__ u32 g_athi[S_LEN * HID / 2];    // attention output, pre-split
__device__ u32 g_atlo[S_LEN * HID / 2];

// ---------------------------------------------------------------------------
// Helpers
// ---------------------------------------------------------------------------
__device__ __forceinline__ u32 pack_bf16(float e0, float e1) {
    __nv_bfloat162 p = __floats2bfloat162_rn(e0, e1);   // .x = e0 (low half)
    return *reinterpret_cast<u32*>(&p);
}

__device__ __forceinline__ void split_pair(float a, float b, u32& hi, u32& lo) {
    float ha = __bfloat162float(__float2bfloat16_rn(a));
    float hb = __bfloat162float(__float2bfloat16_rn(b));
    hi = pack_bf16(ha, hb);
    lo = pack_bf16(a - ha, b - hb);
}

__device__ __forceinline__ void cp16(u32* dst, const u32* src) {
    u32 s = (u32)__cvta_generic_to_shared(dst);
    asm volatile("cp.async.cg.shared.global [%0], [%1], 16;" :: "r"(s), "l"(src));
}

#define MMA_BF16(d, a0, a1, a2, a3, b0, b1)                                 \
    asm volatile(                                                           \
        "mma.sync.aligned.m16n8k16.row.col.f32.bf16.bf16.f32 "              \
        "{%0,%1,%2,%3}, {%4,%5,%6,%7}, {%8,%9}, {%0,%1,%2,%3};"             \
        : "+f"(d[0]), "+f"(d[1]), "+f"(d[2]), "+f"(d[3])                    \
        : "r"(a0), "r"(a1), "r"(a2), "r"(a3), "r"(b0), "r"(b1))

// ---------------------------------------------------------------------------
// Split kernels
// ---------------------------------------------------------------------------
// A-style: pairs along a row. total = M*K/2 words.
__global__ void split_A_kernel(const float* __restrict__ X,
                               u32* __restrict__ hi, u32* __restrict__ lo,
                               int total_words)
{
    int i = blockIdx.x * 256 + threadIdx.x;
    if (i >= total_words) return;
    float2 xy = *(const float2*)(X + (size_t)i * 2);
    split_pair(xy.x, xy.y, hi[i], lo[i]);
}

// B-style: word(kp,n) pairs W[2kp][n] with W[2kp+1][n]; output row stride Nout
// (lets Q/K/V land in one concatenated buffer at column offset noff).
__global__ void split_B_kernel(const float* __restrict__ W,
                               u32* __restrict__ hi, u32* __restrict__ lo,
                               int Kp, int N, int Nout, int noff)
{
    int i = blockIdx.x * 256 + threadIdx.x;
    if (i >= Kp * N) return;
    int kp = i / N;
    int n  = i - kp * N;
    float a = W[(size_t)(2 * kp)     * N + n];
    float b = W[(size_t)(2 * kp + 1) * N + n];
    u32 h, l;
    split_pair(a, b, h, l);
    size_t o = (size_t)kp * Nout + noff + n;
    hi[o] = h;
    lo[o] = l;
}

// ---------------------------------------------------------------------------
// Pre-split bf16x3 GEMM with cp.async double buffering (R5 version, verbatim).
// C[M,N] = A[M,K] @ B[K,N]; A: [M][Kp], B: [Kp][N] pair-word arrays.
// Block tile 128x128, BK=32 (16 pair rows), 256 threads, 2 stages.
// ---------------------------------------------------------------------------
#define RSA 20
#define RSB 136
#define STG_A   (128 * RSA)
#define STG_B   (16 * RSB)
#define STG_WORDS (2 * STG_A + 2 * STG_B)
#define GEMM_SMEM_BYTES (2 * STG_WORDS * 4)

__global__ __launch_bounds__(256, 2) void gemm_pre(
    const u32* __restrict__ Ahi, const u32* __restrict__ Alo,
    const u32* __restrict__ Bhi, const u32* __restrict__ Blo,
    float* __restrict__ C, int M, int N, int Kp)
{
    extern __shared__ u32 smem[];

    const int tid  = threadIdx.x;
    const int warp = tid >> 5;
    const int lane = tid & 31;
    const int wm   = (warp >> 2) * 64;
    const int wn   = (warp & 3)  * 32;
    const int bm   = blockIdx.y * 128;
    const int bn   = blockIdx.x * 128;
    const int r = lane >> 2;
    const int t = lane & 3;

    float acc[4][4][4];
#pragma unroll
    for (int mi = 0; mi < 4; mi++)
#pragma unroll
        for (int ni = 0; ni < 4; ni++)
#pragma unroll
            for (int c = 0; c < 4; c++) acc[mi][ni][c] = 0.f;

    const int KT = Kp / 16;

    auto load_stage = [&](int kt, int buf) {
        u32* base = smem + buf * STG_WORDS;
        u32* sAhi = base;
        u32* sAlo = base + STG_A;
        u32* sBhi = base + 2 * STG_A;
        u32* sBlo = base + 2 * STG_A + STG_B;
        int kp0 = kt * 16;
#pragma unroll
        for (int i = 0; i < 2; i++) {
            int e   = tid + 256 * i;
            int row = e >> 2;
            int c   = e & 3;
            const size_t ga = (size_t)(bm + row) * Kp + kp0 + c * 4;
            cp16(&sAhi[row * RSA + c * 4], Ahi + ga);
            cp16(&sAlo[row * RSA + c * 4], Alo + ga);
        }
#pragma unroll
        for (int i = 0; i < 2; i++) {
            int e    = tid + 256 * i;
            int krow = e >> 5;
            int c    = e & 31;
            const size_t gb = (size_t)(kp0 + krow) * N + bn + c * 4;
            cp16(&sBhi[krow * RSB + c * 4], Bhi + gb);
            cp16(&sBlo[krow * RSB + c * 4], Blo + gb);
        }
    };

    load_stage(0, 0);
    asm volatile("cp.async.commit_group;");

    for (int kt = 0; kt < KT; kt++) {
        if (kt + 1 < KT) {
            load_stage(kt + 1, (kt + 1) & 1);
            asm volatile("cp.async.commit_group;");
            asm volatile("cp.async.wait_group 1;");
        } else {
            asm volatile("cp.async.wait_group 0;");
        }
        __syncthreads();

        u32* base = smem + (kt & 1) * STG_WORDS;
        u32* sAhi = base;
        u32* sAlo = base + STG_A;
        u32* sBhi = base + 2 * STG_A;
        u32* sBlo = base + 2 * STG_A + STG_B;

#pragma unroll
        for (int ks = 0; ks < 2; ks++) {
            u32 bH[4][2], bL[4][2];
#pragma unroll
            for (int ni = 0; ni < 4; ni++) {
                int boff = (ks * 8 + t) * RSB + wn + ni * 8 + r;
                bH[ni][0] = sBhi[boff];
                bH[ni][1] = sBhi[boff + 4 * RSB];
                bL[ni][0] = sBlo[boff];
                bL[ni][1] = sBlo[boff + 4 * RSB];
            }
#pragma unroll
            for (int mi = 0; mi < 4; mi++) {
                int aoff = (wm + mi * 16 + r) * RSA + ks * 8 + t;
                u32 aH0 = sAhi[aoff];
                u32 aH1 = sAhi[aoff + 8 * RSA];
                u32 aH2 = sAhi[aoff + 4];
                u32 aH3 = sAhi[aoff + 8 * RSA + 4];
                u32 aL0 = sAlo[aoff];
                u32 aL1 = sAlo[aoff + 8 * RSA];
                u32 aL2 = sAlo[aoff + 4];
                u32 aL3 = sAlo[aoff + 8 * RSA + 4];
#pragma unroll
                for (int ni = 0; ni < 4; ni++) {
                    MMA_BF16(acc[mi][ni], aH0, aH1, aH2, aH3, bH[ni][0], bH[ni][1]);
                    MMA_BF16(acc[mi][ni], aH0, aH1, aH2, aH3, bL[ni][0], bL[ni][1]);
                    MMA_BF16(acc[mi][ni], aL0, aL1, aL2, aL3, bH[ni][0], bH[ni][1]);
                }
            }
        }
        __syncthreads();
    }

#pragma unroll
    for (int mi = 0; mi < 4; mi++) {
#pragma unroll
        for (int ni = 0; ni < 4; ni++) {
            int row = bm + wm + mi * 16 + r;
            int col = bn + wn + ni * 8 + t * 2;
            *(float2*)(C + (size_t)row * N + col) =
                make_float2(acc[mi][ni][0], acc[mi][ni][1]);
            *(float2*)(C + (size_t)(row + 8) * N + col) =
                make_float2(acc[mi][ni][2], acc[mi][ni][3]);
        }
    }
}

// ---------------------------------------------------------------------------
// RoPE
// ---------------------------------------------------------------------------
__global__ void rope_tables_kernel()
{
    int s = blockIdx.x;
    int d = threadIdx.x;
    double invf = pow(10000.0, -(double)(2 * d) / 128.0);
    float  ang  = (float)s * (float)invf;
    g_cos[s * 64 + d] = (float)cos((double)ang);
    g_sin[s * 64 + d] = (float)sin((double)ang);
}

// Reads from fused qkv buffer (row stride NQKV, column offset coff).
__global__ void rope_split_kernel(const float* __restrict__ x, int coff,
                                  __nv_bfloat16* __restrict__ xhi,
                                  __nv_bfloat16* __restrict__ xlo,
                                  int nheads)
{
    int idx = blockIdx.x * 256 + threadIdx.x;
    int total = S_LEN * nheads * 64;
    if (idx >= total) return;
    int d = idx & 63;
    int t = idx >> 6;
    int h = t % nheads;
    int s = t / nheads;
    float c  = g_cos[s * 64 + d];
    float sn = g_sin[s * 64 + d];
    size_t src = (size_t)s * NQKV + coff + h * HD;
    float x0 = x[src + d];
    float x1 = x[src + d + 64];
    float r0 = x0 * c - x1 * sn;
    float r1 = x1 * c + x0 * sn;
    float h0 = __bfloat162float(__float2bfloat16_rn(r0));
    float h1 = __bfloat162float(__float2bfloat16_rn(r1));
    size_t dst = ((size_t)s * nheads + h) * HD;
    xhi[dst + d]      = __float2bfloat16_rn(h0);
    xhi[dst + d + 64] = __float2bfloat16_rn(h1);
    xlo[dst + d]      = __float2bfloat16_rn(r0 - h0);
    xlo[dst + d + 64] = __float2bfloat16_rn(r1 - h1);
}

// ---------------------------------------------------------------------------
// V split + transpose: g_qkv[s][VOFF + hk*HD + d] -> g_vt{hi,lo} [hk][d][s]
// ---------------------------------------------------------------------------
__global__ __launch_bounds__(256) void v_split_transpose_kernel()
{
    __shared__ float tile[32][33];
    const int s0 = blockIdx.x * 32;
    const int d0 = blockIdx.y * 32;
    const int hk = blockIdx.z;
    const int tx = threadIdx.x;
    const int ty = threadIdx.y;

#pragma unroll
    for (int i = 0; i < 4; i++) {
        int s = s0 + ty + i * 8;
        tile[ty + i * 8][tx] = g_qkv[(size_t)s * NQKV + VOFF + hk * HD + d0 + tx];
    }
    __syncthreads();
#pragma unroll
    for (int i = 0; i < 4; i++) {
        int d = d0 + ty + i * 8;
        float val = tile[tx][ty + i * 8];
        float hi  = __bfloat162float(__float2bfloat16_rn(val));
        size_t o  = ((size_t)hk * HD + d) * S_LEN + s0 + tx;
        g_vthi[o] = __float2bfloat16_rn(hi);
        g_vtlo[o] = __float2bfloat16_rn(val - hi);
    }
}

// ---------------------------------------------------------------------------
// Tensor-core flash attention (bf16x3) — unchanged from R5.
// ---------------------------------------------------------------------------
#define RSQ 68
#define RSV 36
#define SM_QHI 0
#define SM_QLO (64 * RSQ)
#define SM_KHI (2 * 64 * RSQ)
#define SM_KLO (3 * 64 * RSQ)
#define SM_VHI (4 * 64 * RSQ)
#define SM_VLO (4 * 64 * RSQ + 128 * RSV)
#define ATT_SMEM_WORDS (4 * 64 * RSQ + 2 * 128 * RSV)

__global__ __launch_bounds__(128) void attn_mma_kernel(
    const __nv_bfloat16* __restrict__ qhi, const __nv_bfloat16* __restrict__ qlo,
    const __nv_bfloat16* __restrict__ khi, const __nv_bfloat16* __restrict__ klo,
    const __nv_bfloat16* __restrict__ vthi, const __nv_bfloat16* __restrict__ vtlo,
    u32* __restrict__ athi, u32* __restrict__ atlo)
{
    extern __shared__ u32 sm[];
    u32* Qhi = sm + SM_QHI;
    u32* Qlo = sm + SM_QLO;
    u32* Khi = sm + SM_KHI;
    u32* Klo = sm + SM_KLO;
    u32* Vhi = sm + SM_VHI;
    u32* Vlo = sm + SM_VLO;

    const int tid  = threadIdx.x;
    const int warp = tid >> 5;
    const int lane = tid & 31;
    const int g    = lane >> 2;
    const int t4   = lane & 3;
    const int q0   = blockIdx.x * 64;
    const int h    = blockIdx.y;
    const int hk   = h >> 2;
    const int wrow = warp * 16;

    const float NEGINF = __int_as_float(0xff800000);

#pragma unroll
    for (int it = 0; it < 8; it++) {
        int e   = tid + 128 * it;
        int row = e >> 4;
        int c   = e & 15;
        size_t gb = ((size_t)(q0 + row) * NH + h) * HD + c * 8;
        *(uint4*)&Qhi[row * RSQ + c * 4] = *(const uint4*)(qhi + gb);
        *(uint4*)&Qlo[row * RSQ + c * 4] = *(const uint4*)(qlo + gb);
    }

    const int i0 = q0 + wrow + g;
    const int i1 = i0 + 8;

    float oacc[16][4];
#pragma unroll
    for (int n = 0; n < 16; n++)
#pragma unroll
        for (int c = 0; c < 4; c++) oacc[n][c] = 0.f;
    float m0 = -1e30f, m1 = -1e30f, l0 = 0.f, l1 = 0.f;

    int lo_j = q0 - (WINDOW - 1);
    if (lo_j < 0) lo_j = 0;
    const int jt_lo = lo_j >> 6;
    const int jt_hi = q0 >> 6;

    for (int jt = jt_lo; jt <= jt_hi; jt++) {
        const int j0 = jt << 6;
        __syncthreads();
#pragma unroll
        for (int it = 0; it < 8; it++) {
            int e = tid + 128 * it;
            {
                int row = e >> 4, c = e & 15;
                size_t gb = ((size_t)(j0 + row) * NKV + hk) * HD + c * 8;
                *(uint4*)&Khi[row * RSQ + c * 4] = *(const uint4*)(khi + gb);
                *(uint4*)&Klo[row * RSQ + c * 4] = *(const uint4*)(klo + gb);
            }
            {
                int d = e >> 3, c = e & 7;
                size_t gb = ((size_t)hk * HD + d) * S_LEN + j0 + c * 8;
                *(uint4*)&Vhi[d * RSV + c * 4] = *(const uint4*)(vthi + gb);
                *(uint4*)&Vlo[d * RSV + c * 4] = *(const uint4*)(vtlo + gb);
            }
        }
        __syncthreads();

        float sacc[8][4];
#pragma unroll
        for (int n = 0; n < 8; n++)
#pragma unroll
            for (int c = 0; c < 4; c++) sacc[n][c] = 0.f;

#pragma unroll
        for (int kt = 0; kt < 8; kt++) {
            int ao = (wrow + g) * RSQ + kt * 8 + t4;
            u32 qh0 = Qhi[ao];
            u32 qh1 = Qhi[ao + 8 * RSQ];
            u32 qh2 = Qhi[ao + 4];
            u32 qh3 = Qhi[ao + 8 * RSQ + 4];
            u32 ql0 = Qlo[ao];
            u32 ql1 = Qlo[ao + 8 * RSQ];
            u32 ql2 = Qlo[ao + 4];
            u32 ql3 = Qlo[ao + 8 * RSQ + 4];
#pragma unroll
            for (int nt = 0; nt < 8; nt++) {
                int bo = (nt * 8 + g) * RSQ + kt * 8 + t4;
                u32 bh0 = Khi[bo], bh1 = Khi[bo + 4];
                u32 bl0 = Klo[bo], bl1 = Klo[bo + 4];
                MMA_BF16(sacc[nt], qh0, qh1, qh2, qh3, bh0, bh1);
                MMA_BF16(sacc[nt], qh0, qh1, qh2, qh3, bl0, bl1);
                MMA_BF16(sacc[nt], ql0, ql1, ql2, ql3, bh0, bh1);
            }
        }

        bool full = (j0 + 63 <= q0 + wrow) && (j0 > q0 + wrow + 15 - WINDOW);
        if (full) {
#pragma unroll
            for (int nt = 0; nt < 8; nt++)
#pragma unroll
                for (int c = 0; c < 4; c++) sacc[nt][c] *= SCALE_F;
        } else {
#pragma unroll
            for (int nt = 0; nt < 8; nt++) {
                int jb = j0 + nt * 8 + 2 * t4;
                bool a00 = (jb     <= i0) && (jb     > i0 - WINDOW);
                bool a01 = (jb + 1 <= i0) && (jb + 1 > i0 - WINDOW);
                bool a10 = (jb     <= i1) && (jb     > i1 - WINDOW);
                bool a11 = (jb + 1 <= i1) && (jb + 1 > i1 - WINDOW);
                sacc[nt][0] = a00 ? sacc[nt][0] * SCALE_F : NEGINF;
                sacc[nt][1] = a01 ? sacc[nt][1] * SCALE_F : NEGINF;
                sacc[nt][2] = a10 ? sacc[nt][2] * SCALE_F : NEGINF;
                sacc[nt][3] = a11 ? sacc[nt][3] * SCALE_F : NEGINF;
            }
        }

        float mx0 = -1e30f, mx1 = -1e30f;
#pragma unroll
        for (int nt = 0; nt < 8; nt++) {
            mx0 = fmaxf(mx0, fmaxf(sacc[nt][0], sacc[nt][1]));
            mx1 = fmaxf(mx1, fmaxf(sacc[nt][2], sacc[nt][3]));
        }
        mx0 = fmaxf(mx0, __shfl_xor_sync(0xffffffffu, mx0, 1));
        mx0 = fmaxf(mx0, __shfl_xor_sync(0xffffffffu, mx0, 2));
        mx1 = fmaxf(mx1, __shfl_xor_sync(0xffffffffu, mx1, 1));
        mx1 = fmaxf(mx1, __shfl_xor_sync(0xffffffffu, mx1, 2));
        float mn0 = fmaxf(m0, mx0);
        float mn1 = fmaxf(m1, mx1);
        float f0 = __expf(m0 - mn0);
        float f1 = __expf(m1 - mn1);
        float sum0 = 0.f, sum1 = 0.f;
#pragma unroll
        for (int nt = 0; nt < 8; nt++) {
            sacc[nt][0] = __expf(sacc[nt][0] - mn0); sum0 += sacc[nt][0];
            sacc[nt][1] = __expf(sacc[nt][1] - mn0); sum0 += sacc[nt][1];
            sacc[nt][2] = __expf(sacc[nt][2] - mn1); sum1 += sacc[nt][2];
            sacc[nt][3] = __expf(sacc[nt][3] - mn1); sum1 += sacc[nt][3];
        }
        sum0 += __shfl_xor_sync(0xffffffffu, sum0, 1);
        sum0 += __shfl_xor_sync(0xffffffffu, sum0, 2);
        sum1 += __shfl_xor_sync(0xffffffffu, sum1, 1);
        sum1 += __shfl_xor_sync(0xffffffffu, sum1, 2);
        l0 = l0 * f0 + sum0;  m0 = mn0;
        l1 = l1 * f1 + sum1;  m1 = mn1;

#pragma unroll
        for (int n = 0; n < 16; n++) {
            oacc[n][0] *= f0; oacc[n][1] *= f0;
            oacc[n][2] *= f1; oacc[n][3] *= f1;
        }

#pragma unroll
        for (int kt = 0; kt < 4; kt++) {
            float p00 = sacc[2*kt][0],   p01 = sacc[2*kt][1];
            float p02 = sacc[2*kt][2],   p03 = sacc[2*kt][3];
            float p10 = sacc[2*kt+1][0], p11 = sacc[2*kt+1][1];
            float p12 = sacc[2*kt+1][2], p13 = sacc[2*kt+1][3];
            float h00 = __bfloat162float(__float2bfloat16_rn(p00));
            float h01 = __bfloat162float(__float2bfloat16_rn(p01));
            float h02 = __bfloat162float(__float2bfloat16_rn(p02));
            float h03 = __bfloat162float(__float2bfloat16_rn(p03));
            float h10 = __bfloat162float(__float2bfloat16_rn(p10));
            float h11 = __bfloat162float(__float2bfloat16_rn(p11));
            float h12 = __bfloat162float(__float2bfloat16_rn(p12));
            float h13 = __bfloat162float(__float2bfloat16_rn(p13));
            u32 ah0 = pack_bf16(h00, h01);
            u32 ah1 = pack_bf16(h02, h03);
            u32 ah2 = pack_bf16(h10, h11);
            u32 ah3 = pack_bf16(h12, h13);
            u32 al0 = pack_bf16(p00 - h00, p01 - h01);
            u32 al1 = pack_bf16(p02 - h02, p03 - h03);
            u32 al2 = pack_bf16(p10 - h10, p11 - h11);
            u32 al3 = pack_bf16(p12 - h12, p13 - h13);
#pragma unroll
            for (int nt = 0; nt < 16; nt++) {
                int vo = (nt * 8 + g) * RSV + kt * 8 + t4;
                u32 vh0 = Vhi[vo], vh1 = Vhi[vo + 4];
                u32 vl0 = Vlo[vo], vl1 = Vlo[vo + 4];
                MMA_BF16(oacc[nt], ah0, ah1, ah2, ah3, vh0, vh1);
                MMA_BF16(oacc[nt], ah0, ah1, ah2, ah3, vl0, vl1);
                MMA_BF16(oacc[nt], al0, al1, al2, al3, vh0, vh1);
            }
        }
    }

    float inv0 = 1.0f / l0;
    float inv1 = 1.0f / l1;
#pragma unroll
    for (int nt = 0; nt < 16; nt++) {
        int col = nt * 8 + 2 * t4;
        int wcol = (h * HD + col) >> 1;
        size_t w0 = (size_t)i0 * (HID / 2) + wcol;
        size_t w1 = (size_t)i1 * (HID / 2) + wcol;
        u32 hi0, lo0, hi1, lo1;
        split_pair(oacc[nt][0] * inv0, oacc[nt][1] * inv0, hi0, lo0);
        split_pair(oacc[nt][2] * inv1, oacc[nt][3] * inv1, hi1, lo1);
        athi[w0] = hi0;  atlo[w0] = lo0;
        athi[w1] = hi1;  atlo[w1] = lo1;
    }
}

// ---------------------------------------------------------------------------
// kernel_launch
// ---------------------------------------------------------------------------
extern "C" void kernel_launch(void* const* d_in, const int* in_sizes, int n_in,
                              void* d_out, int out_size)
{
    (void)in_sizes; (void)n_in; (void)out_size;
    const float* hs = (const float*)d_in[0];
    const float* Wq = (const float*)d_in[3];
    const float* Wk = (const float*)d_in[4];
    const float* Wv = (const float*)d_in[5];
    const float* Wo = (const float*)d_in[6];
    float* out = (float*)d_out;

    float* qkv;
    __nv_bfloat16 *qhi, *qlo, *khi, *klo, *vthi, *vtlo;
    u32 *hshi, *hslo, *wqkvhi, *wqkvlo, *wohi, *wolo, *athi, *atlo;
    cudaGetSymbolAddress((void**)&qkv,    g_qkv);
    cudaGetSymbolAddress((void**)&qhi,    g_qhi);
    cudaGetSymbolAddress((void**)&qlo,    g_qlo);
    cudaGetSymbolAddress((void**)&khi,    g_khi);
    cudaGetSymbolAddress((void**)&klo,    g_klo);
    cudaGetSymbolAddress((void**)&vthi,   g_vthi);
    cudaGetSymbolAddress((void**)&vtlo,   g_vtlo);
    cudaGetSymbolAddress((void**)&hshi,   g_hshi);
    cudaGetSymbolAddress((void**)&hslo,   g_hslo);
    cudaGetSymbolAddress((void**)&wqkvhi, g_wqkvhi);
    cudaGetSymbolAddress((void**)&wqkvlo, g_wqkvlo);
    cudaGetSymbolAddress((void**)&wohi,   g_wohi);
    cudaGetSymbolAddress((void**)&wolo,   g_wolo);
    cudaGetSymbolAddress((void**)&athi,   g_athi);
    cudaGetSymbolAddress((void**)&atlo,   g_atlo);

    cudaFuncSetAttribute(gemm_pre,
                         cudaFuncAttributeMaxDynamicSharedMemorySize, GEMM_SMEM_BYTES);
    const int att_smem = ATT_SMEM_WORDS * (int)sizeof(u32);
    cudaFuncSetAttribute(attn_mma_kernel,
                         cudaFuncAttributeMaxDynamicSharedMemorySize, att_smem);

    // ---- operand pre-split (QKV weights into one fused [Kp][6144] buffer) ----
    {
        int wA = S_LEN * HID / 2;
        split_A_kernel<<<(wA + 255) / 256, 256>>>(hs, hshi, hslo, wA);
        int wQ = (HID / 2) * (NH * HD);
        split_B_kernel<<<(wQ + 255) / 256, 256>>>(Wq, wqkvhi, wqkvlo,
                                                  HID / 2, NH * HD, NQKV, 0);
        int wK = (HID / 2) * (NKV * HD);
        split_B_kernel<<<(wK + 255) / 256, 256>>>(Wk, wqkvhi, wqkvlo,
                                                  HID / 2, NKV * HD, NQKV, KOFF);
        split_B_kernel<<<(wK + 255) / 256, 256>>>(Wv, wqkvhi, wqkvlo,
                                                  HID / 2, NKV * HD, NQKV, VOFF);
        int wO = (NH * HD / 2) * HID;
        split_B_kernel<<<(wO + 255) / 256, 256>>>(Wo, wohi, wolo,
                                                  NH * HD / 2, HID, HID, 0);
    }

    // ---- fused QKV projection (one wave-efficient GEMM) ----
    gemm_pre<<<dim3(NQKV / 128, S_LEN / 128), 256, GEMM_SMEM_BYTES>>>(
        hshi, hslo, wqkvhi, wqkvlo, qkv, S_LEN, NQKV, HID / 2);

    // ---- RoPE + splits ----
    rope_tables_kernel<<<S_LEN, 64>>>();
    rope_split_kernel<<<(S_LEN * NH  * 64 + 255) / 256, 256>>>(qkv, 0,    qhi, qlo, NH);
    rope_split_kernel<<<(S_LEN * NKV * 64 + 255) / 256, 256>>>(qkv, KOFF, khi, klo, NKV);
    v_split_transpose_kernel<<<dim3(S_LEN / 32, HD / 32, NKV), dim3(32, 8)>>>();

    // ---- attention ----
    attn_mma_kernel<<<dim3(S_LEN / 64, NH), 128, att_smem>>>(
        qhi, qlo, khi, klo, vthi, vtlo, athi, atlo);

    // ---- output projection ----
    gemm_pre<<<dim3(HID / 128, S_LEN / 128), 256, GEMM_SMEM_BYTES>>>(
        athi, atlo, wohi, wolo, out, S_LEN, HID, NH * HD / 2);
}